// round 1
// baseline (speedup 1.0000x reference)
#include <cuda_runtime.h>

// Problem constants (fixed shapes from setup_inputs)
#define HDIM 512
#define WDIM 512
#define HS 54
#define PH 51               // HS - WIN + 1
#define NPOS (PH*PH)        // 2601
#define CROP 64
#define STRIDE_I 8          // floor((512-70)/54)
#define RF_I 70

// Per-batch crop coordinates (scratch: __device__ globals, no allocation)
__device__ int g_axH[64];   // ax[:,0] = row coord (H axis)
__device__ int g_axW[64];   // ax[:,1] = col coord (W axis)

// ---------------------------------------------------------------------------
// Kernel 1: per-batch argmax over score_map[b,0,:51,:51], first-index tiebreak
// ---------------------------------------------------------------------------
__global__ void argmax_kernel(const float* __restrict__ score) {
    int b = blockIdx.x;
    __shared__ float svals[256];
    __shared__ int   sidx[256];
    int t = threadIdx.x;
    float best = -__int_as_float(0x7f800000); // -inf
    int bi = NPOS;
    for (int i = t; i < NPOS; i += 256) {
        int r = i / PH, c = i % PH;
        float v = score[b * (HS*HS) + r * HS + c];
        if (v > best) { best = v; bi = i; }   // loop index increasing => first occurrence kept
    }
    svals[t] = best; sidx[t] = bi;
    __syncthreads();
    for (int s = 128; s > 0; s >>= 1) {
        if (t < s) {
            float v2 = svals[t + s]; int i2 = sidx[t + s];
            if (v2 > svals[t] || (v2 == svals[t] && i2 < sidx[t])) {
                svals[t] = v2; sidx[t] = i2;
            }
        }
        __syncthreads();
    }
    if (t == 0) {
        int idx  = sidx[0];
        float bv = svals[0];
        int x = (bv > 0.0f) ? (idx / PH) : 0;   // ax[:,0] source
        int y = (bv > 0.0f) ? (idx % PH) : 0;   // ax[:,1] source
        g_axH[b] = x * STRIDE_I + RF_I;
        g_axW[b] = y * STRIDE_I + RF_I;
    }
}

// ---------------------------------------------------------------------------
// Kernel 2: bulk copy real_AB -> fake_ABm region of out (float4 vectorized)
// ---------------------------------------------------------------------------
__global__ void copy_kernel(const float4* __restrict__ src, float4* __restrict__ dst, int n4) {
    int i = blockIdx.x * blockDim.x + threadIdx.x;
    if (i < n4) dst[i] = src[i];
}

// ---------------------------------------------------------------------------
// Kernel 3: pixel replacement fake_ABm[b,:,axH,axW] = fake_AB[b,:,axH,axW]
// ---------------------------------------------------------------------------
__global__ void fixup_kernel(const float* __restrict__ fakeAB, float* __restrict__ out, int B) {
    int t = blockIdx.x * blockDim.x + threadIdx.x;
    if (t >= B * 6) return;
    int b = t / 6, c = t % 6;
    long long off = ((long long)b * 6 + c) * (HDIM * WDIM)
                  + (long long)g_axH[b] * WDIM + g_axW[b];
    out[off] = fakeAB[off];
}

// ---------------------------------------------------------------------------
// Kernel 4: crop-and-resize for real_B and fake_B.
// Replicates reference fp32 math exactly (no FMA on the coordinate path).
// ---------------------------------------------------------------------------
__global__ void crop_kernel(const float* __restrict__ realB,
                            const float* __restrict__ fakeB,
                            float* __restrict__ out_real,
                            float* __restrict__ out_fake,
                            int B) {
    int gid = blockIdx.x * blockDim.x + threadIdx.x;
    int per = B * 3 * CROP * CROP;
    if (gid >= 2 * per) return;
    int which = (gid >= per) ? 1 : 0;          // 0 = real, 1 = fake
    int lid = gid - which * per;

    int j = lid & (CROP - 1);                  // W-axis output index
    int i = (lid >> 6) & (CROP - 1);           // H-axis output index
    int c = (lid >> 12) % 3;
    int b = lid / (3 * CROP * CROP);

    const float* img = (which ? fakeB : realB) + ((long long)b * 3 + c) * (HDIM * WDIM);
    float* dst = which ? out_fake : out_real;

    float axH = (float)g_axH[b];
    float axW = (float)g_axW[b];

    // _boxes: ny0 = axH/511, nx0 = axW/511, nh = nw = 63/511 (all exact-sequence fp32)
    const float inv_den = 0.0f; (void)inv_den;
    float nh  = __fdiv_rn(63.0f, (float)(HDIM - 1));
    float ny0 = __fdiv_rn(axH, (float)(HDIM - 1));
    float nx0 = __fdiv_rn(axW, (float)(WDIM - 1));
    float ny1 = __fadd_rn(ny0, nh);
    float nx1 = __fadd_rn(nx0, nh);
    float dy  = __fsub_rn(ny1, ny0);
    float dx  = __fsub_rn(nx1, nx0);

    // ys = ny0*(H-1) + ((i * dy) * (H-1)) / (CROP-1)   (left-to-right fp32)
    float ys = __fadd_rn(__fmul_rn(ny0, (float)(HDIM - 1)),
                         __fdiv_rn(__fmul_rn(__fmul_rn((float)i, dy), (float)(HDIM - 1)),
                                   (float)(CROP - 1)));
    float xs = __fadd_rn(__fmul_rn(nx0, (float)(WDIM - 1)),
                         __fdiv_rn(__fmul_rn(__fmul_rn((float)j, dx), (float)(WDIM - 1)),
                                   (float)(CROP - 1)));

    bool vy = (ys >= 0.0f) && (ys <= (float)(HDIM - 1));
    bool vx = (xs >= 0.0f) && (xs <= (float)(WDIM - 1));

    float y0f = floorf(ys);
    float x0f = floorf(xs);
    int y0 = (int)fminf(fmaxf(y0f, 0.0f), (float)(HDIM - 1));
    int x0 = (int)fminf(fmaxf(x0f, 0.0f), (float)(WDIM - 1));
    int y1 = min(y0 + 1, HDIM - 1);
    int x1 = min(x0 + 1, WDIM - 1);

    float ly = __fsub_rn(ys, y0f);
    float lx = __fsub_rn(xs, x0f);

    float v00 = img[(long long)y0 * WDIM + x0];
    float v01 = img[(long long)y0 * WDIM + x1];
    float v10 = img[(long long)y1 * WDIM + x0];
    float v11 = img[(long long)y1 * WDIM + x1];

    float one_lx = __fsub_rn(1.0f, lx);
    float one_ly = __fsub_rn(1.0f, ly);
    float top = __fadd_rn(__fmul_rn(one_lx, v00), __fmul_rn(lx, v01));
    float bot = __fadd_rn(__fmul_rn(one_lx, v10), __fmul_rn(lx, v11));
    float val = __fadd_rn(__fmul_rn(one_ly, top), __fmul_rn(ly, bot));

    dst[lid] = (vy && vx) ? val : 0.0f;
}

// ---------------------------------------------------------------------------
extern "C" void kernel_launch(void* const* d_in, const int* in_sizes, int n_in,
                              void* d_out, int out_size) {
    const float* real_AB   = (const float*)d_in[0];
    const float* fake_AB   = (const float*)d_in[1];
    const float* score_map = (const float*)d_in[2];
    const float* real_B    = (const float*)d_in[3];
    const float* fake_B    = (const float*)d_in[4];
    float* out = (float*)d_out;

    int B = in_sizes[2] / (HS * HS);              // 16
    long long abm_elems = (long long)B * 6 * HDIM * WDIM;      // 25,165,824
    long long crop_elems = (long long)B * 3 * CROP * CROP;     // 196,608

    float* out_abm  = out;
    float* out_real = out + abm_elems;
    float* out_fake = out + abm_elems + crop_elems;

    // 1. localize
    argmax_kernel<<<B, 256>>>(score_map);

    // 2. bulk copy real_AB -> fake_ABm (float4)
    int n4 = (int)(abm_elems / 4);
    copy_kernel<<<(n4 + 255) / 256, 256>>>((const float4*)real_AB, (float4*)out_abm, n4);

    // 3. pixel replace (depends on 1 & 2; stream order serializes)
    fixup_kernel<<<1, 128>>>(fake_AB, out_abm, B);

    // 4. crops (depends on 1)
    int total = (int)(2 * crop_elems);
    crop_kernel<<<(total + 255) / 256, 256>>>(real_B, fake_B, out_real, out_fake, B);
}

// round 2
// speedup vs baseline: 1.0428x; 1.0428x over previous
#include <cuda_runtime.h>

// Problem constants (fixed shapes from setup_inputs)
#define HDIM 512
#define WDIM 512
#define HW   (HDIM*WDIM)          // 262144
#define HW4  (HW/4)               // 65536 float4 per plane
#define HS 54
#define PH 51                     // HS - WIN + 1
#define NPOS (PH*PH)              // 2601
#define CROP 64
#define STRIDE_I 8                // floor((512-70)/54)
#define RF_I 70

// Per-batch crop/patch coordinates (scratch: __device__ globals, no allocation)
__device__ int g_axH[64];         // ax[:,0] = row coord (H axis)
__device__ int g_axW[64];         // ax[:,1] = col coord (W axis)
__device__ int g_off4[64];        // plane-local float4 index of patched pixel
__device__ int g_lane[64];        // lane within that float4

// ---------------------------------------------------------------------------
// Kernel 1: per-batch argmax over score_map[b,0,:51,:51], first-index tiebreak
// ---------------------------------------------------------------------------
__global__ void argmax_kernel(const float* __restrict__ score) {
    int b = blockIdx.x;
    __shared__ float svals[256];
    __shared__ int   sidx[256];
    int t = threadIdx.x;
    float best = -__int_as_float(0x7f800000); // -inf
    int bi = NPOS;
    for (int i = t; i < NPOS; i += 256) {
        int r = i / PH, c = i % PH;
        float v = score[b * (HS*HS) + r * HS + c];
        if (v > best) { best = v; bi = i; }   // increasing index => first occurrence
    }
    svals[t] = best; sidx[t] = bi;
    __syncthreads();
    for (int s = 128; s > 0; s >>= 1) {
        if (t < s) {
            float v2 = svals[t + s]; int i2 = sidx[t + s];
            if (v2 > svals[t] || (v2 == svals[t] && i2 < sidx[t])) {
                svals[t] = v2; sidx[t] = i2;
            }
        }
        __syncthreads();
    }
    if (t == 0) {
        int idx  = sidx[0];
        float bv = svals[0];
        int x = (bv > 0.0f) ? (idx / PH) : 0;   // ax[:,0]
        int y = (bv > 0.0f) ? (idx % PH) : 0;   // ax[:,1]
        int axH = x * STRIDE_I + RF_I;
        int axW = y * STRIDE_I + RF_I;
        g_axH[b] = axH;
        g_axW[b] = axW;
        int off  = axH * WDIM + axW;            // plane-local element index
        g_off4[b] = off >> 2;
        g_lane[b] = off & 3;
    }
}

// ---------------------------------------------------------------------------
// Kernel 2 (fused): crop blocks first (overlap), then copy+patch blocks.
// ---------------------------------------------------------------------------
#define CROP_THREADS_TOTAL (2 * 16 * 3 * CROP * CROP)     // 393216
#define CROP_BLOCKS        (CROP_THREADS_TOTAL / 256)     // 1536

__global__ __launch_bounds__(256) void fused_kernel(
        const float4* __restrict__ realAB4,
        const float*  __restrict__ fakeAB,
        const float*  __restrict__ realB,
        const float*  __restrict__ fakeB,
        float4* __restrict__ out_abm4,
        float*  __restrict__ out_real,
        float*  __restrict__ out_fake,
        int n4, int B)
{
    if (blockIdx.x >= CROP_BLOCKS) {
        // ---------------- bulk copy + pixel patch ----------------
        int i = (blockIdx.x - CROP_BLOCKS) * 256 + threadIdx.x;
        if (i >= n4) return;
        int plane = i >> 16;                 // which (b,c) plane (HW4 = 65536)
        int b = plane / 6;
        float4 v = realAB4[i];
        if ((i & (HW4 - 1)) == g_off4[b]) {
            int lane = g_lane[b];
            ((float*)&v)[lane] = fakeAB[(long long)4 * i + lane];
        }
        out_abm4[i] = v;
        return;
    }

    // ---------------- crop-and-resize (exact fp32 sequence) ----------------
    int gid = blockIdx.x * 256 + threadIdx.x;
    int per = B * 3 * CROP * CROP;
    int which = (gid >= per) ? 1 : 0;          // 0 = real, 1 = fake
    int lid = gid - which * per;

    int j = lid & (CROP - 1);                  // W-axis output index
    int i = (lid >> 6) & (CROP - 1);           // H-axis output index
    int c = (lid >> 12) % 3;
    int b = lid / (3 * CROP * CROP);

    const float* img = (which ? fakeB : realB) + ((long long)b * 3 + c) * HW;
    float* dst = which ? out_fake : out_real;

    float axH = (float)g_axH[b];
    float axW = (float)g_axW[b];

    float nh  = __fdiv_rn(63.0f, (float)(HDIM - 1));
    float ny0 = __fdiv_rn(axH, (float)(HDIM - 1));
    float nx0 = __fdiv_rn(axW, (float)(WDIM - 1));
    float ny1 = __fadd_rn(ny0, nh);
    float nx1 = __fadd_rn(nx0, nh);
    float dy  = __fsub_rn(ny1, ny0);
    float dx  = __fsub_rn(nx1, nx0);

    float ys = __fadd_rn(__fmul_rn(ny0, (float)(HDIM - 1)),
                         __fdiv_rn(__fmul_rn(__fmul_rn((float)i, dy), (float)(HDIM - 1)),
                                   (float)(CROP - 1)));
    float xs = __fadd_rn(__fmul_rn(nx0, (float)(WDIM - 1)),
                         __fdiv_rn(__fmul_rn(__fmul_rn((float)j, dx), (float)(WDIM - 1)),
                                   (float)(CROP - 1)));

    bool vy = (ys >= 0.0f) && (ys <= (float)(HDIM - 1));
    bool vx = (xs >= 0.0f) && (xs <= (float)(WDIM - 1));

    float y0f = floorf(ys);
    float x0f = floorf(xs);
    int y0 = (int)fminf(fmaxf(y0f, 0.0f), (float)(HDIM - 1));
    int x0 = (int)fminf(fmaxf(x0f, 0.0f), (float)(WDIM - 1));
    int y1 = min(y0 + 1, HDIM - 1);
    int x1 = min(x0 + 1, WDIM - 1);

    float ly = __fsub_rn(ys, y0f);
    float lx = __fsub_rn(xs, x0f);

    float v00 = img[(long long)y0 * WDIM + x0];
    float v01 = img[(long long)y0 * WDIM + x1];
    float v10 = img[(long long)y1 * WDIM + x0];
    float v11 = img[(long long)y1 * WDIM + x1];

    float one_lx = __fsub_rn(1.0f, lx);
    float one_ly = __fsub_rn(1.0f, ly);
    float top = __fadd_rn(__fmul_rn(one_lx, v00), __fmul_rn(lx, v01));
    float bot = __fadd_rn(__fmul_rn(one_lx, v10), __fmul_rn(lx, v11));
    float val = __fadd_rn(__fmul_rn(one_ly, top), __fmul_rn(ly, bot));

    dst[lid] = (vy && vx) ? val : 0.0f;
}

// ---------------------------------------------------------------------------
extern "C" void kernel_launch(void* const* d_in, const int* in_sizes, int n_in,
                              void* d_out, int out_size) {
    const float* real_AB   = (const float*)d_in[0];
    const float* fake_AB   = (const float*)d_in[1];
    const float* score_map = (const float*)d_in[2];
    const float* real_B    = (const float*)d_in[3];
    const float* fake_B    = (const float*)d_in[4];
    float* out = (float*)d_out;

    int B = in_sizes[2] / (HS * HS);                           // 16
    long long abm_elems  = (long long)B * 6 * HW;              // 25,165,824
    long long crop_elems = (long long)B * 3 * CROP * CROP;     // 196,608

    float* out_abm  = out;
    float* out_real = out + abm_elems;
    float* out_fake = out + abm_elems + crop_elems;

    // 1. localize (writes g_axH/g_axW/g_off4/g_lane; stream order = dependency)
    argmax_kernel<<<B, 256>>>(score_map);

    // 2. fused: crop blocks first (overlap with copy), then copy+patch
    int n4 = (int)(abm_elems / 4);                             // 6,291,456
    int copy_blocks = (n4 + 255) / 256;                        // 24,576
    fused_kernel<<<CROP_BLOCKS + copy_blocks, 256>>>(
        (const float4*)real_AB, fake_AB, real_B, fake_B,
        (float4*)out_abm, out_real, out_fake, n4, B);
}

// round 3
// speedup vs baseline: 1.1396x; 1.0928x over previous
#include <cuda_runtime.h>

// Problem constants (fixed shapes from setup_inputs)
#define HDIM 512
#define WDIM 512
#define HW   (HDIM*WDIM)          // 262144
#define HW4  (HW/4)               // 65536 float4 per plane
#define HS 54
#define PH 51                     // HS - WIN + 1
#define NPOS (PH*PH)              // 2601
#define CROP 64
#define STRIDE_I 8                // floor((512-70)/54)
#define RF_I 70

// Per-batch crop/patch coordinates (scratch: __device__ globals, no allocation)
__device__ int g_axH[64];         // ax[:,0] = row coord (H axis)
__device__ int g_axW[64];         // ax[:,1] = col coord (W axis)
__device__ int g_off4[64];        // plane-local float4 index of patched pixel
__device__ int g_lane[64];        // lane within that float4

// ---------------------------------------------------------------------------
// Kernel 1: per-batch argmax over score_map[b,0,:51,:51], first-index tiebreak
// ---------------------------------------------------------------------------
__global__ void argmax_kernel(const float* __restrict__ score) {
    int b = blockIdx.x;
    __shared__ float svals[256];
    __shared__ int   sidx[256];
    int t = threadIdx.x;
    float best = -__int_as_float(0x7f800000); // -inf
    int bi = NPOS;
    for (int i = t; i < NPOS; i += 256) {
        int r = i / PH, c = i % PH;
        float v = score[b * (HS*HS) + r * HS + c];
        if (v > best) { best = v; bi = i; }   // increasing index => first occurrence
    }
    svals[t] = best; sidx[t] = bi;
    __syncthreads();
    for (int s = 128; s > 0; s >>= 1) {
        if (t < s) {
            float v2 = svals[t + s]; int i2 = sidx[t + s];
            if (v2 > svals[t] || (v2 == svals[t] && i2 < sidx[t])) {
                svals[t] = v2; sidx[t] = i2;
            }
        }
        __syncthreads();
    }
    if (t == 0) {
        int idx  = sidx[0];
        float bv = svals[0];
        int x = (bv > 0.0f) ? (idx / PH) : 0;   // ax[:,0]
        int y = (bv > 0.0f) ? (idx % PH) : 0;   // ax[:,1]
        int axH = x * STRIDE_I + RF_I;
        int axW = y * STRIDE_I + RF_I;
        g_axH[b] = axH;
        g_axW[b] = axW;
        int off  = axH * WDIM + axW;            // plane-local element index
        g_off4[b] = off >> 2;
        g_lane[b] = off & 3;
    }
}

// ---------------------------------------------------------------------------
// Kernel 2 (fused): crop blocks first (overlap), then copy+patch blocks.
// Copy blocks: 1024 contiguous float4 per block, 4 per thread, MLP=4.
// ---------------------------------------------------------------------------
#define CROP_THREADS_TOTAL (2 * 16 * 3 * CROP * CROP)     // 393216
#define CROP_BLOCKS        (CROP_THREADS_TOTAL / 256)     // 1536
#define F4_PER_BLOCK       1024
#define COPY_BLOCKS        (6291456 / F4_PER_BLOCK)       // 6144 (exact)

__global__ __launch_bounds__(256) void fused_kernel(
        const float4* __restrict__ realAB4,
        const float*  __restrict__ fakeAB,
        const float*  __restrict__ realB,
        const float*  __restrict__ fakeB,
        float4* __restrict__ out_abm4,
        float*  __restrict__ out_real,
        float*  __restrict__ out_fake,
        int B)
{
    if (blockIdx.x >= CROP_BLOCKS) {
        // ---------------- bulk copy + pixel patch ----------------
        int cIdx  = blockIdx.x - CROP_BLOCKS;
        int base4 = cIdx * F4_PER_BLOCK;           // block-aligned within a plane
        int plane = base4 >> 16;                   // HW4 = 65536 float4/plane
        int b     = plane / 6;                     // uniform per block
        int loff  = g_off4[b];                     // plane-local patched float4
        int blk_lo = base4 & (HW4 - 1);
        bool has_patch = (loff >= blk_lo) && (loff < blk_lo + F4_PER_BLOCK);

        int i0 = base4 + threadIdx.x;
        float4 v0 = __ldcs(realAB4 + i0);
        float4 v1 = __ldcs(realAB4 + i0 + 256);
        float4 v2 = __ldcs(realAB4 + i0 + 512);
        float4 v3 = __ldcs(realAB4 + i0 + 768);

        if (has_patch) {
            int lane = g_lane[b];
            int local = (i0 & (HW4 - 1));
            #pragma unroll
            for (int k = 0; k < 4; k++) {
                if (local + k * 256 == loff) {
                    float4* vp = (k == 0) ? &v0 : (k == 1) ? &v1 : (k == 2) ? &v2 : &v3;
                    ((float*)vp)[lane] = fakeAB[(long long)4 * (i0 + k * 256) + lane];
                }
            }
        }
        __stcs(out_abm4 + i0,       v0);
        __stcs(out_abm4 + i0 + 256, v1);
        __stcs(out_abm4 + i0 + 512, v2);
        __stcs(out_abm4 + i0 + 768, v3);
        return;
    }

    // ---------------- crop-and-resize (exact fp32 sequence) ----------------
    int gid = blockIdx.x * 256 + threadIdx.x;
    int per = B * 3 * CROP * CROP;
    int which = (gid >= per) ? 1 : 0;          // 0 = real, 1 = fake
    int lid = gid - which * per;

    int j = lid & (CROP - 1);                  // W-axis output index
    int i = (lid >> 6) & (CROP - 1);           // H-axis output index
    int c = (lid >> 12) % 3;
    int b = lid / (3 * CROP * CROP);

    const float* img = (which ? fakeB : realB) + ((long long)b * 3 + c) * HW;
    float* dst = which ? out_fake : out_real;

    float axH = (float)g_axH[b];
    float axW = (float)g_axW[b];

    float nh  = __fdiv_rn(63.0f, (float)(HDIM - 1));
    float ny0 = __fdiv_rn(axH, (float)(HDIM - 1));
    float nx0 = __fdiv_rn(axW, (float)(WDIM - 1));
    float ny1 = __fadd_rn(ny0, nh);
    float nx1 = __fadd_rn(nx0, nh);
    float dy  = __fsub_rn(ny1, ny0);
    float dx  = __fsub_rn(nx1, nx0);

    float ys = __fadd_rn(__fmul_rn(ny0, (float)(HDIM - 1)),
                         __fdiv_rn(__fmul_rn(__fmul_rn((float)i, dy), (float)(HDIM - 1)),
                                   (float)(CROP - 1)));
    float xs = __fadd_rn(__fmul_rn(nx0, (float)(WDIM - 1)),
                         __fdiv_rn(__fmul_rn(__fmul_rn((float)j, dx), (float)(WDIM - 1)),
                                   (float)(CROP - 1)));

    bool vy = (ys >= 0.0f) && (ys <= (float)(HDIM - 1));
    bool vx = (xs >= 0.0f) && (xs <= (float)(WDIM - 1));

    float y0f = floorf(ys);
    float x0f = floorf(xs);
    int y0 = (int)fminf(fmaxf(y0f, 0.0f), (float)(HDIM - 1));
    int x0 = (int)fminf(fmaxf(x0f, 0.0f), (float)(WDIM - 1));
    int y1 = min(y0 + 1, HDIM - 1);
    int x1 = min(x0 + 1, WDIM - 1);

    float ly = __fsub_rn(ys, y0f);
    float lx = __fsub_rn(xs, x0f);

    float v00 = img[(long long)y0 * WDIM + x0];
    float v01 = img[(long long)y0 * WDIM + x1];
    float v10 = img[(long long)y1 * WDIM + x0];
    float v11 = img[(long long)y1 * WDIM + x1];

    float one_lx = __fsub_rn(1.0f, lx);
    float one_ly = __fsub_rn(1.0f, ly);
    float top = __fadd_rn(__fmul_rn(one_lx, v00), __fmul_rn(lx, v01));
    float bot = __fadd_rn(__fmul_rn(one_lx, v10), __fmul_rn(lx, v11));
    float val = __fadd_rn(__fmul_rn(one_ly, top), __fmul_rn(ly, bot));

    dst[lid] = (vy && vx) ? val : 0.0f;
}

// ---------------------------------------------------------------------------
extern "C" void kernel_launch(void* const* d_in, const int* in_sizes, int n_in,
                              void* d_out, int out_size) {
    const float* real_AB   = (const float*)d_in[0];
    const float* fake_AB   = (const float*)d_in[1];
    const float* score_map = (const float*)d_in[2];
    const float* real_B    = (const float*)d_in[3];
    const float* fake_B    = (const float*)d_in[4];
    float* out = (float*)d_out;

    int B = in_sizes[2] / (HS * HS);                           // 16
    long long abm_elems  = (long long)B * 6 * HW;              // 25,165,824
    long long crop_elems = (long long)B * 3 * CROP * CROP;     // 196,608

    float* out_abm  = out;
    float* out_real = out + abm_elems;
    float* out_fake = out + abm_elems + crop_elems;

    // 1. localize (writes g_axH/g_axW/g_off4/g_lane; stream order = dependency)
    argmax_kernel<<<B, 256>>>(score_map);

    // 2. fused: crop blocks first (overlap with copy), then copy+patch
    fused_kernel<<<CROP_BLOCKS + COPY_BLOCKS, 256>>>(
        (const float4*)real_AB, fake_AB, real_B, fake_B,
        (float4*)out_abm, out_real, out_fake, B);
}